// round 9
// baseline (speedup 1.0000x reference)
#include <cuda_runtime.h>
#include <cuda_bf16.h>
#include <cstdint>

#define L 2048
#define HID 4096
#define NH 32
#define NKV 8
#define HD 128
#define MAXP 4096

// ---------------------------------------------------------------------------
// PTX helpers (sm_80-class instructions only: valid on baseline sm_103 target)
// ---------------------------------------------------------------------------
__device__ __forceinline__ uint32_t smem_u32(const void* p) {
    uint32_t a;
    asm("{ .reg .u64 t; cvta.to.shared.u64 t, %1; cvt.u32.u64 %0, t; }" : "=r"(a) : "l"(p));
    return a;
}
__device__ __forceinline__ float fast_exp2(float x) {
    float y;
    asm("ex2.approx.f32 %0, %1;" : "=f"(y) : "f"(x));
    return y;
}
#define LDSM_X4(r0, r1, r2, r3, addr)                                              \
    asm volatile("ldmatrix.sync.aligned.m8n8.x4.shared.b16 {%0,%1,%2,%3}, [%4];"   \
                 : "=r"(r0), "=r"(r1), "=r"(r2), "=r"(r3) : "r"(addr))
#define LDSM_X4_T(r0, r1, r2, r3, addr)                                            \
    asm volatile("ldmatrix.sync.aligned.m8n8.x4.trans.shared.b16 {%0,%1,%2,%3}, [%4];" \
                 : "=r"(r0), "=r"(r1), "=r"(r2), "=r"(r3) : "r"(addr))
#define MMA_BF16(d, a, b)                                                          \
    asm volatile("mma.sync.aligned.m16n8k16.row.col.f32.bf16.bf16.f32 "            \
                 "{%0,%1,%2,%3}, {%4,%5,%6,%7}, {%8,%9}, {%0,%1,%2,%3};"           \
                 : "+f"((d)[0]), "+f"((d)[1]), "+f"((d)[2]), "+f"((d)[3])          \
                 : "r"((a)[0]), "r"((a)[1]), "r"((a)[2]), "r"((a)[3]),             \
                   "r"((b)[0]), "r"((b)[1]))
#define CP_ASYNC16(dst, src)                                                       \
    asm volatile("cp.async.cg.shared.global [%0], [%1], 16;" :: "r"(dst), "l"(src))
#define CP_COMMIT() asm volatile("cp.async.commit_group;" ::: "memory")
#define CP_WAIT(n) asm volatile("cp.async.wait_group %0;" :: "n"(n) : "memory")

// ---------------------------------------------------------------------------
// scratch (device globals; no runtime alloc)
// ---------------------------------------------------------------------------
#define NW_TOTAL 41943040
#define OFF_WQ 0
#define OFF_WK 16777216
#define OFF_WV 20971520
#define OFF_WO 25165824

__device__ __nv_bfloat16 g_h_hi[(size_t)L * HID];
__device__ __nv_bfloat16 g_h_lo[(size_t)L * HID];
__device__ __nv_bfloat16 g_w_hi[(size_t)NW_TOTAL];
__device__ __nv_bfloat16 g_w_lo[(size_t)NW_TOTAL];
__device__ __nv_bfloat16 g_a_hi[(size_t)L * HID];
__device__ __nv_bfloat16 g_a_lo[(size_t)L * HID];
__device__ __nv_bfloat16 g_qh[(size_t)L * HID];
__device__ __nv_bfloat16 g_ql[(size_t)L * HID];
__device__ __nv_bfloat16 g_kh[(size_t)L * NKV * HD];
__device__ __nv_bfloat16 g_kl[(size_t)L * NKV * HD];
__device__ __nv_bfloat16 g_vb[(size_t)L * NKV * HD];
__device__ float g_q[(size_t)L * HID];
__device__ float g_k[(size_t)L * NKV * HD];
__device__ float g_v[(size_t)L * NKV * HD];

__device__ __forceinline__ void split_bf16(float x, __nv_bfloat16& hi, __nv_bfloat16& lo) {
    hi = __float2bfloat16_rn(x);
    lo = __float2bfloat16_rn(x - __bfloat162float(hi));
}
__device__ __forceinline__ uint32_t pack_bf16(float lo, float hi) {
    __nv_bfloat162 t = __floats2bfloat162_rn(lo, hi);  // .x = lo bits [15:0]
    return *(uint32_t*)&t;
}

// ---------------------------------------------------------------------------
// cache copy — rows [L, MAXP) only (rope_kv fully writes rows [0, L))
// ---------------------------------------------------------------------------
__global__ void copy_caches_kernel(const float4* __restrict__ kin,
                                   const float4* __restrict__ vin,
                                   float4* __restrict__ kout,
                                   float4* __restrict__ vout) {
    int idx = blockIdx.x * 256 + threadIdx.x;
    const int n4 = (MAXP - L) * NKV * HD / 4;  // 524288
    const int off = L * NKV * HD / 4;
    if (idx < n4) kout[off + idx] = kin[off + idx];
    else vout[off + idx - n4] = vin[off + idx - n4];
}

// ---------------------------------------------------------------------------
// fused weight split-convert (all 4 weights, one launch)
// ---------------------------------------------------------------------------
__global__ void convert_all_kernel(const float4* __restrict__ wq,
                                   const float4* __restrict__ wk,
                                   const float4* __restrict__ wv,
                                   const float4* __restrict__ wo,
                                   __nv_bfloat16* __restrict__ hi,
                                   __nv_bfloat16* __restrict__ lo) {
    int i = blockIdx.x * 256 + threadIdx.x;  // [0, NW_TOTAL/4)
    const float4* src;
    int base;
    if (i < OFF_WK / 4) { src = wq; base = 0; }
    else if (i < OFF_WV / 4) { src = wk; base = OFF_WK / 4; }
    else if (i < OFF_WO / 4) { src = wv; base = OFF_WV / 4; }
    else { src = wo; base = OFF_WO / 4; }
    float4 v = src[i - base];
    __nv_bfloat16 h0, h1, h2, h3, l0, l1, l2, l3;
    split_bf16(v.x, h0, l0); split_bf16(v.y, h1, l1);
    split_bf16(v.z, h2, l2); split_bf16(v.w, h3, l3);
    __nv_bfloat162* hp = (__nv_bfloat162*)(hi + (size_t)i * 4);
    __nv_bfloat162* lp = (__nv_bfloat162*)(lo + (size_t)i * 4);
    hp[0] = __nv_bfloat162(h0, h1); hp[1] = __nv_bfloat162(h2, h3);
    lp[0] = __nv_bfloat162(l0, l1); lp[1] = __nv_bfloat162(l2, l3);
}

// ---------------------------------------------------------------------------
// RMSNorm -> split bf16
// ---------------------------------------------------------------------------
__global__ void __launch_bounds__(256) rmsnorm_kernel(const float* __restrict__ x,
                                                      const float* __restrict__ w) {
    int row = blockIdx.x;
    const float* xr = x + (size_t)row * HID;
    int t = threadIdx.x;
    float vals[16];
    float local = 0.f;
#pragma unroll
    for (int i = 0; i < 16; ++i) {
        float v = xr[t + i * 256];
        vals[i] = v;
        local += v * v;
    }
    __shared__ float red[8];
#pragma unroll
    for (int o = 16; o; o >>= 1) local += __shfl_xor_sync(0xffffffffu, local, o);
    if ((t & 31) == 0) red[t >> 5] = local;
    __syncthreads();
    if (t < 8) {
        float v = red[t];
#pragma unroll
        for (int o = 4; o; o >>= 1) v += __shfl_xor_sync(0xffu, v, o);
        if (t == 0) red[0] = v;
    }
    __syncthreads();
    float rms = rsqrtf(red[0] / (float)HID + 1e-5f);
    size_t base = (size_t)row * HID;
#pragma unroll
    for (int i = 0; i < 16; ++i) {
        float y = vals[i] * rms * w[t + i * 256];
        __nv_bfloat16 h, l;
        split_bf16(y, h, l);
        g_h_hi[base + t + i * 256] = h;
        g_h_lo[base + t + i * 256] = l;
    }
}

// ---------------------------------------------------------------------------
// split-bf16 GEMM via mma.sync: C[M,N] = A[M,K] B[N,K]^T (+res), K=4096
// CTA 128x256, 8 warps (2x4), warp tile 64x64, K-chunk 64, 2-stage cp.async.
// Term-major MMAs in N-halves of 4 (reuse distance 16) — keeps the RAW chain
// broken while capping live B-fragments at 16 regs (round-8 hit regs=255).
// MODE 1: fused QKV (N=6144; route q/k/v).  MODE 2: +res.
// ---------------------------------------------------------------------------
#define GSTRIDE 144
#define ATILE 18432            // 128 * 144
#define BTILE 36864            // 256 * 144
#define BOFF  36864            // 2 * ATILE
#define GSTAGE 110592          // 2*ATILE + 2*BTILE
#define GEMM_SMEM (2 * GSTAGE) // 221184

template <int MODE>
__global__ void __launch_bounds__(256, 1) mma_gemm_kernel(
    const __nv_bfloat16* __restrict__ Ah, const __nv_bfloat16* __restrict__ Al,
    const __nv_bfloat16* __restrict__ Bh, const __nv_bfloat16* __restrict__ Bl,
    float* __restrict__ C, float* __restrict__ Ck, float* __restrict__ Cvv,
    int N, const float* __restrict__ res) {
    extern __shared__ char sm[];
    const uint32_t sb = smem_u32(sm);
    const int tid = threadIdx.x;
    const int lane = tid & 31, w = tid >> 5;
    const int wm = w >> 2, wn = w & 3;          // 2 x 4 warps
    const int bm = blockIdx.y * 128, bn = blockIdx.x * 256;

    float acc[4][8][4];
#pragma unroll
    for (int a = 0; a < 4; ++a)
#pragma unroll
        for (int b = 0; b < 8; ++b)
#pragma unroll
            for (int c = 0; c < 4; ++c) acc[a][b][c] = 0.f;

    auto issue = [&](int c, int s) {
#pragma unroll
        for (int j = 0; j < 8; ++j) {
            const int term = j >> 2;
            const int local = tid + (j & 3) * 256;   // 0..1023
            const int row = local >> 3;              // 0..127
            const int seg = local & 7;
            const __nv_bfloat16* src = term ? Al : Ah;
            const void* g = src + (size_t)(bm + row) * HID + c * 64 + seg * 8;
            uint32_t dst = sb + s * GSTAGE + term * ATILE + row * GSTRIDE + seg * 16;
            CP_ASYNC16(dst, g);
        }
#pragma unroll
        for (int j = 0; j < 16; ++j) {
            const int term = j >> 3;
            const int local = tid + (j & 7) * 256;   // 0..2047
            const int row = local >> 3;              // 0..255
            const int seg = local & 7;
            const __nv_bfloat16* src = term ? Bl : Bh;
            const void* g = src + (size_t)(bn + row) * HID + c * 64 + seg * 8;
            uint32_t dst = sb + s * GSTAGE + BOFF + term * BTILE + row * GSTRIDE + seg * 16;
            CP_ASYNC16(dst, g);
        }
    };

    auto compute = [&](int s) {
        const uint32_t base = sb + s * GSTAGE;
        const int rsel = lane & 15;
        const int csel = (lane >> 4) << 4;
#pragma unroll
        for (int ks = 0; ks < 4; ++ks) {
            uint32_t ah[4][4], al[4][4];
#pragma unroll
            for (int mt = 0; mt < 4; ++mt) {
                uint32_t ad = base + (wm * 64 + mt * 16 + rsel) * GSTRIDE + ks * 32 + csel;
                LDSM_X4(ah[mt][0], ah[mt][1], ah[mt][2], ah[mt][3], ad);
                LDSM_X4(al[mt][0], al[mt][1], al[mt][2], al[mt][3], ad + ATILE);
            }
            // N processed in two halves of 4 tiles: live B-frags = 16 regs,
            // term-major within each half (acc reuse distance 16 MMAs).
#pragma unroll
            for (int half = 0; half < 2; ++half) {
                uint32_t bh[4][2], bl[4][2];
#pragma unroll
                for (int g = 0; g < 2; ++g) {
                    uint32_t bd = base + BOFF +
                                  (wn * 64 + (half * 2 + g) * 16 + rsel) * GSTRIDE +
                                  ks * 32 + csel;
                    uint32_t t0, t1, t2, t3;
                    LDSM_X4(t0, t1, t2, t3, bd);
                    bh[2 * g][0] = t0; bh[2 * g][1] = t2;
                    bh[2 * g + 1][0] = t1; bh[2 * g + 1][1] = t3;
                    LDSM_X4(t0, t1, t2, t3, bd + BTILE);
                    bl[2 * g][0] = t0; bl[2 * g][1] = t2;
                    bl[2 * g + 1][0] = t1; bl[2 * g + 1][1] = t3;
                }
#pragma unroll
                for (int nt = 0; nt < 4; ++nt)
#pragma unroll
                    for (int mt = 0; mt < 4; ++mt)
                        MMA_BF16(acc[mt][half * 4 + nt], ah[mt], bh[nt]);
#pragma unroll
                for (int nt = 0; nt < 4; ++nt)
#pragma unroll
                    for (int mt = 0; mt < 4; ++mt)
                        MMA_BF16(acc[mt][half * 4 + nt], ah[mt], bl[nt]);
#pragma unroll
                for (int nt = 0; nt < 4; ++nt)
#pragma unroll
                    for (int mt = 0; mt < 4; ++mt)
                        MMA_BF16(acc[mt][half * 4 + nt], al[mt], bh[nt]);
            }
        }
    };

    issue(0, 0); CP_COMMIT();
    issue(1, 1); CP_COMMIT();
#pragma unroll 1
    for (int c = 0; c < 64; ++c) {
        if (c + 1 < 64) { CP_WAIT(1); } else { CP_WAIT(0); }
        __syncthreads();
        compute(c & 1);
        if (c + 2 < 64) {
            __syncthreads();
            issue(c + 2, c & 1);
            CP_COMMIT();
        }
    }

    // epilogue: route output
    float* Cout = C;
    int ncols = N, bnl = bn;
    if (MODE == 1) {
        if (bn < 4096) { Cout = C; ncols = 4096; bnl = bn; }
        else if (bn < 5120) { Cout = Ck; ncols = 1024; bnl = bn - 4096; }
        else { Cout = Cvv; ncols = 1024; bnl = bn - 5120; }
    }
#pragma unroll
    for (int mt = 0; mt < 4; ++mt)
#pragma unroll
        for (int nt = 0; nt < 8; ++nt) {
            int row = bm + wm * 64 + mt * 16 + (lane >> 2);
            int col = bnl + wn * 64 + nt * 8 + ((lane & 3) << 1);
            size_t o0 = (size_t)row * ncols + col;
            size_t o1 = (size_t)(row + 8) * ncols + col;
            float2 v0 = make_float2(acc[mt][nt][0], acc[mt][nt][1]);
            float2 v1 = make_float2(acc[mt][nt][2], acc[mt][nt][3]);
            if (MODE == 2) {
                float2 r0 = *(const float2*)&res[o0];
                float2 r1 = *(const float2*)&res[o1];
                v0.x += r0.x; v0.y += r0.y;
                v1.x += r1.x; v1.y += r1.y;
            }
            *(float2*)&Cout[o0] = v0;
            *(float2*)&Cout[o1] = v1;
        }
}

// ---------------------------------------------------------------------------
// RoPE Q: fp32 in g_q -> scaled (1/sqrt(hd) * log2e) split bf16
// ---------------------------------------------------------------------------
__global__ void rope_q_kernel(const float* __restrict__ cosb, const float* __restrict__ sinb) {
    const float QS = 0.08838834764831845f * 1.4426950408889634f;
    int idx = blockIdx.x * 256 + threadIdx.x;
    int d = idx & 63;
    int h = (idx >> 6) & (NH - 1);
    int i = idx >> 11;
    const float* qp = g_q + (size_t)i * HID + h * HD;
    float c0 = cosb[i * HD + d], s0 = sinb[i * HD + d];
    float c1 = cosb[i * HD + d + 64], s1 = sinb[i * HD + d + 64];
    float q0 = qp[d], q1 = qp[d + 64];
    float r0 = (q0 * c0 - q1 * s0) * QS;
    float r1 = (q1 * c1 + q0 * s1) * QS;
    size_t base = (size_t)i * HID + h * HD;
    __nv_bfloat16 hh, ll;
    split_bf16(r0, hh, ll);
    g_qh[base + d] = hh; g_ql[base + d] = ll;
    split_bf16(r1, hh, ll);
    g_qh[base + d + 64] = hh; g_ql[base + d + 64] = ll;
}

// RoPE K + scatter fp32 caches + split bf16 K, bf16 V (position = row index)
__global__ void rope_kv_kernel(const float* __restrict__ cosb, const float* __restrict__ sinb,
                               float* __restrict__ kc_out, float* __restrict__ vc_out) {
    int idx = blockIdx.x * 256 + threadIdx.x;
    int d = idx & 63;
    int h = (idx >> 6) & (NKV - 1);
    int i = idx >> 9;
    size_t base = (size_t)i * (NKV * HD) + h * HD;
    float c0 = cosb[i * HD + d], s0 = sinb[i * HD + d];
    float c1 = cosb[i * HD + d + 64], s1 = sinb[i * HD + d + 64];
    float k0 = g_k[base + d], k1 = g_k[base + d + 64];
    float k0n = k0 * c0 - k1 * s0;
    float k1n = k1 * c1 + k0 * s1;
    kc_out[base + d] = k0n;
    kc_out[base + d + 64] = k1n;
    __nv_bfloat16 hh, ll;
    split_bf16(k0n, hh, ll);
    g_kh[base + d] = hh; g_kl[base + d] = ll;
    split_bf16(k1n, hh, ll);
    g_kh[base + d + 64] = hh; g_kl[base + d + 64] = ll;
    float v0 = g_v[base + d], v1 = g_v[base + d + 64];
    vc_out[base + d] = v0;
    vc_out[base + d + 64] = v1;
    g_vb[base + d] = __float2bfloat16_rn(v0);
    g_vb[base + d + 64] = __float2bfloat16_rn(v1);
}

// ---------------------------------------------------------------------------
// Flash attention via mma.sync: BM=128 (8 warps x m16), BN=64, HD=128.
// QK^T split bf16, term-major in N-halves of 4 (register-pressure capped);
// softmax fp32 exp2; PV bf16 via ldmatrix.trans.
// Split cp.async waits: V load overlaps the whole S-phase.
// ---------------------------------------------------------------------------
#define FSTRIDE 272
#define FQH 0
#define FQL 34816
#define FKH 69632
#define FKL 87040
#define FV 104448
#define FLASH_SMEM 121856

__global__ void __launch_bounds__(256, 1) flash_kernel() {
    extern __shared__ char sm[];
    const uint32_t sb = smem_u32(sm);
    const int tid = threadIdx.x;
    const int lane = tid & 31, w = tid >> 5;
    const int qt = gridDim.x - 1 - blockIdx.x;  // heavy tiles first
    const int head = blockIdx.y;
    const int kvh = head >> 2;
    const int rsel = lane & 15;
    const int csel = (lane >> 4) << 4;

#pragma unroll
    for (int j = 0; j < 16; ++j) {
        const int term = j >> 3;
        const int local = tid + (j & 7) * 256;
        const int row = local >> 4;
        const int seg = local & 15;
        const __nv_bfloat16* src = (term ? g_ql : g_qh);
        const void* g = src + (size_t)(qt * 128 + row) * HID + head * HD + seg * 8;
        uint32_t dst = sb + (term ? FQL : FQH) + row * FSTRIDE + seg * 16;
        CP_ASYNC16(dst, g);
    }
    CP_COMMIT();

    float o_[16][4];
#pragma unroll
    for (int n = 0; n < 16; ++n)
#pragma unroll
        for (int c = 0; c < 4; ++c) o_[n][c] = 0.f;
    float m_[2] = {-1e30f, -1e30f};
    float l_[2] = {0.f, 0.f};

    const int kt_end = 2 * qt + 2;
#pragma unroll 1
    for (int kt = 0; kt < kt_end; ++kt) {
        __syncthreads();
#pragma unroll
        for (int j = 0; j < 8; ++j) {
            const int t = j >> 2;
            const int local = tid + (j & 3) * 256;
            const int row = local >> 4;
            const int seg = local & 15;
            const __nv_bfloat16* src = (t == 0) ? g_kh : g_kl;
            const void* g = src + (size_t)(kt * 64 + row) * (NKV * HD) + kvh * HD + seg * 8;
            uint32_t dst = sb + ((t == 0) ? FKH : FKL) + row * FSTRIDE + seg * 16;
            CP_ASYNC16(dst, g);
        }
        CP_COMMIT();
#pragma unroll
        for (int j = 0; j < 4; ++j) {
            const int local = tid + j * 256;
            const int row = local >> 4;
            const int seg = local & 15;
            const void* g = g_vb + (size_t)(kt * 64 + row) * (NKV * HD) + kvh * HD + seg * 8;
            uint32_t dst = sb + FV + row * FSTRIDE + seg * 16;
            CP_ASYNC16(dst, g);
        }
        CP_COMMIT();

        CP_WAIT(1);
        __syncthreads();

        // S = Q' K^T, term-major in halves of 4 (live B-frags capped at 16 regs)
        float s[8][4];
#pragma unroll
        for (int n = 0; n < 8; ++n)
#pragma unroll
            for (int c = 0; c < 4; ++c) s[n][c] = 0.f;
#pragma unroll
        for (int ks = 0; ks < 8; ++ks) {
            uint32_t ah[4], al[4];
            uint32_t aaddr = sb + FQH + (w * 16 + rsel) * FSTRIDE + ks * 32 + csel;
            LDSM_X4(ah[0], ah[1], ah[2], ah[3], aaddr);
            LDSM_X4(al[0], al[1], al[2], al[3], aaddr + (FQL - FQH));
#pragma unroll
            for (int half = 0; half < 2; ++half) {
                uint32_t bh[4][2], bl[4][2];
#pragma unroll
                for (int g = 0; g < 2; ++g) {
                    uint32_t bd = sb + FKH +
                                  ((half * 2 + g) * 16 + rsel) * FSTRIDE + ks * 32 + csel;
                    uint32_t t0, t1, t2, t3;
                    LDSM_X4(t0, t1, t2, t3, bd);
                    bh[2 * g][0] = t0; bh[2 * g][1] = t2;
                    bh[2 * g + 1][0] = t1; bh[2 * g + 1][1] = t3;
                    LDSM_X4(t0, t1, t2, t3, bd + (FKL - FKH));
                    bl[2 * g][0] = t0; bl[2 * g][1] = t2;
                    bl[2 * g + 1][0] = t1; bl[2 * g + 1][1] = t3;
                }
#pragma unroll
                for (int n = 0; n < 4; ++n) MMA_BF16(s[half * 4 + n], ah, bh[n]);
#pragma unroll
                for (int n = 0; n < 4; ++n) MMA_BF16(s[half * 4 + n], ah, bl[n]);
#pragma unroll
                for (int n = 0; n < 4; ++n) MMA_BF16(s[half * 4 + n], al, bh[n]);
            }
        }

        if (kt >= 2 * qt) {
            const int r0g = qt * 128 + w * 16 + (lane >> 2);
#pragma unroll
            for (int j = 0; j < 8; ++j) {
                int cb = kt * 64 + j * 8 + ((lane & 3) << 1);
                if (cb > r0g) s[j][0] = -1e30f;
                if (cb + 1 > r0g) s[j][1] = -1e30f;
                if (cb > r0g + 8) s[j][2] = -1e30f;
                if (cb + 1 > r0g + 8) s[j][3] = -1e30f;
            }
        }

#pragma unroll
        for (int i = 0; i < 2; ++i) {
            float mt_ = -1e30f;
#pragma unroll
            for (int j = 0; j < 8; ++j)
                mt_ = fmaxf(mt_, fmaxf(s[j][2 * i], s[j][2 * i + 1]));
            mt_ = fmaxf(mt_, __shfl_xor_sync(0xffffffffu, mt_, 1));
            mt_ = fmaxf(mt_, __shfl_xor_sync(0xffffffffu, mt_, 2));
            float mn = fmaxf(m_[i], mt_);
            float corr = fast_exp2(m_[i] - mn);
            m_[i] = mn;
            float rs = 0.f;
#pragma unroll
            for (int j = 0; j < 8; ++j) {
                float p0 = fast_exp2(s[j][2 * i] - mn);
                float p1 = fast_exp2(s[j][2 * i + 1] - mn);
                s[j][2 * i] = p0;
                s[j][2 * i + 1] = p1;
                rs += p0 + p1;
            }
            rs += __shfl_xor_sync(0xffffffffu, rs, 1);
            rs += __shfl_xor_sync(0xffffffffu, rs, 2);
            l_[i] = l_[i] * corr + rs;
#pragma unroll
            for (int n = 0; n < 16; ++n) {
                o_[n][2 * i] *= corr;
                o_[n][2 * i + 1] *= corr;
            }
        }

        uint32_t pa[4][4];
#pragma unroll
        for (int t = 0; t < 4; ++t) {
            pa[t][0] = pack_bf16(s[2 * t][0], s[2 * t][1]);
            pa[t][1] = pack_bf16(s[2 * t][2], s[2 * t][3]);
            pa[t][2] = pack_bf16(s[2 * t + 1][0], s[2 * t + 1][1]);
            pa[t][3] = pack_bf16(s[2 * t + 1][2], s[2 * t + 1][3]);
        }

        CP_WAIT(0);
        __syncthreads();

#pragma unroll
        for (int t = 0; t < 4; ++t) {
#pragma unroll
            for (int g = 0; g < 8; ++g) {
                uint32_t vaddr = sb + FV + (t * 16 + rsel) * FSTRIDE +
                                 (g * 16 + ((lane >> 4) << 3)) * 2;
                uint32_t t0, t1, t2, t3;
                LDSM_X4_T(t0, t1, t2, t3, vaddr);
                uint32_t b0[2] = {t0, t1}, b1[2] = {t2, t3};
                MMA_BF16(o_[2 * g], pa[t], b0);
                MMA_BF16(o_[2 * g + 1], pa[t], b1);
            }
        }
    }

    const float inv0 = 1.f / l_[0];
    const float inv1 = 1.f / l_[1];
    const int r0g = qt * 128 + w * 16 + (lane >> 2);
#pragma unroll
    for (int nt = 0; nt < 16; ++nt) {
        int col = head * HD + nt * 8 + ((lane & 3) << 1);
        size_t o0 = (size_t)r0g * HID + col;
        size_t o1 = o0 + (size_t)8 * HID;
        __nv_bfloat16 h0, l0, h1, l1;
        split_bf16(o_[nt][0] * inv0, h0, l0);
        split_bf16(o_[nt][1] * inv0, h1, l1);
        *(__nv_bfloat162*)(g_a_hi + o0) = __nv_bfloat162(h0, h1);
        *(__nv_bfloat162*)(g_a_lo + o0) = __nv_bfloat162(l0, l1);
        split_bf16(o_[nt][2] * inv1, h0, l0);
        split_bf16(o_[nt][3] * inv1, h1, l1);
        *(__nv_bfloat162*)(g_a_hi + o1) = __nv_bfloat162(h0, h1);
        *(__nv_bfloat162*)(g_a_lo + o1) = __nv_bfloat162(l0, l1);
    }
}

// ---------------------------------------------------------------------------
// launch
// ---------------------------------------------------------------------------
extern "C" void kernel_launch(void* const* d_in, const int* in_sizes, int n_in,
                              void* d_out, int out_size) {
    const float* x = (const float*)d_in[0];
    const float* cosb = (const float*)d_in[1];
    const float* sinb = (const float*)d_in[2];
    // d_in[3] position_ids (arange; not dereferenced), d_in[4] seq_len
    const float* kc_in = (const float*)d_in[5];
    const float* vc_in = (const float*)d_in[6];
    const float* lnw = (const float*)d_in[7];
    const float* Wq = (const float*)d_in[8];
    const float* Wk = (const float*)d_in[9];
    const float* Wv = (const float*)d_in[10];
    const float* Wo = (const float*)d_in[11];

    float* out = (float*)d_out;
    float* kc_out = out + (size_t)L * HID;
    float* vc_out = kc_out + (size_t)MAXP * NKV * HD;

    __nv_bfloat16 *pHh, *pHl, *pWh, *pWl, *pAh, *pAl;
    float *pQ, *pK, *pV;
    cudaGetSymbolAddress((void**)&pHh, g_h_hi);
    cudaGetSymbolAddress((void**)&pHl, g_h_lo);
    cudaGetSymbolAddress((void**)&pWh, g_w_hi);
    cudaGetSymbolAddress((void**)&pWl, g_w_lo);
    cudaGetSymbolAddress((void**)&pAh, g_a_hi);
    cudaGetSymbolAddress((void**)&pAl, g_a_lo);
    cudaGetSymbolAddress((void**)&pQ, g_q);
    cudaGetSymbolAddress((void**)&pK, g_k);
    cudaGetSymbolAddress((void**)&pV, g_v);

    // caches: rows [L, MAXP) copied; rows [0, L) fully written by rope_kv
    copy_caches_kernel<<<(2 * (MAXP - L) * NKV * HD / 4) / 256, 256>>>(
        (const float4*)kc_in, (const float4*)vc_in, (float4*)kc_out, (float4*)vc_out);

    convert_all_kernel<<<(NW_TOTAL / 4) / 256, 256>>>(
        (const float4*)Wq, (const float4*)Wk, (const float4*)Wv, (const float4*)Wo, pWh, pWl);

    rmsnorm_kernel<<<L, 256>>>(x, lnw);

    cudaFuncSetAttribute((const void*)mma_gemm_kernel<1>,
                         cudaFuncAttributeMaxDynamicSharedMemorySize, GEMM_SMEM);
    cudaFuncSetAttribute((const void*)mma_gemm_kernel<2>,
                         cudaFuncAttributeMaxDynamicSharedMemorySize, GEMM_SMEM);

    // fused Q+K+V projection: N = 4096 + 1024 + 1024 = 6144, grid (24, 16)
    mma_gemm_kernel<1><<<dim3(6144 / 256, L / 128), 256, GEMM_SMEM>>>(
        pHh, pHl, pWh, pWl, pQ, pK, pV, 6144, nullptr);

    rope_q_kernel<<<(L * NH * 64) / 256, 256>>>(cosb, sinb);
    rope_kv_kernel<<<(L * NKV * 64) / 256, 256>>>(cosb, sinb, kc_out, vc_out);

    cudaFuncSetAttribute(flash_kernel, cudaFuncAttributeMaxDynamicSharedMemorySize, FLASH_SMEM);
    flash_kernel<<<dim3(L / 128, NH), 256, FLASH_SMEM>>>();

    mma_gemm_kernel<2><<<dim3(HID / 256, L / 128), 256, GEMM_SMEM>>>(
        pAh, pAl, pWh + OFF_WO, pWl + OFF_WO, out, nullptr, nullptr, HID, x);
}

// round 10
// speedup vs baseline: 1.0287x; 1.0287x over previous
#include <cuda_runtime.h>
#include <cuda_bf16.h>
#include <cstdint>

#define L 2048
#define HID 4096
#define NH 32
#define NKV 8
#define HD 128
#define MAXP 4096

// ---------------------------------------------------------------------------
// PTX helpers (sm_80-class instructions only: valid on baseline sm_103 target)
// ---------------------------------------------------------------------------
__device__ __forceinline__ uint32_t smem_u32(const void* p) {
    uint32_t a;
    asm("{ .reg .u64 t; cvta.to.shared.u64 t, %1; cvt.u32.u64 %0, t; }" : "=r"(a) : "l"(p));
    return a;
}
__device__ __forceinline__ float fast_exp2(float x) {
    float y;
    asm("ex2.approx.f32 %0, %1;" : "=f"(y) : "f"(x));
    return y;
}
#define LDSM_X4(r0, r1, r2, r3, addr)                                              \
    asm volatile("ldmatrix.sync.aligned.m8n8.x4.shared.b16 {%0,%1,%2,%3}, [%4];"   \
                 : "=r"(r0), "=r"(r1), "=r"(r2), "=r"(r3) : "r"(addr))
#define LDSM_X4_T(r0, r1, r2, r3, addr)                                            \
    asm volatile("ldmatrix.sync.aligned.m8n8.x4.trans.shared.b16 {%0,%1,%2,%3}, [%4];" \
                 : "=r"(r0), "=r"(r1), "=r"(r2), "=r"(r3) : "r"(addr))
#define MMA_BF16(d, a, b)                                                          \
    asm volatile("mma.sync.aligned.m16n8k16.row.col.f32.bf16.bf16.f32 "            \
                 "{%0,%1,%2,%3}, {%4,%5,%6,%7}, {%8,%9}, {%0,%1,%2,%3};"           \
                 : "+f"((d)[0]), "+f"((d)[1]), "+f"((d)[2]), "+f"((d)[3])          \
                 : "r"((a)[0]), "r"((a)[1]), "r"((a)[2]), "r"((a)[3]),             \
                   "r"((b)[0]), "r"((b)[1]))
#define CP_ASYNC16(dst, src)                                                       \
    asm volatile("cp.async.cg.shared.global [%0], [%1], 16;" :: "r"(dst), "l"(src))
#define CP_COMMIT() asm volatile("cp.async.commit_group;" ::: "memory")
#define CP_WAIT(n) asm volatile("cp.async.wait_group %0;" :: "n"(n) : "memory")

// ---------------------------------------------------------------------------
// scratch (device globals; no runtime alloc)
// ---------------------------------------------------------------------------
#define NW_TOTAL 41943040
#define OFF_WQ 0
#define OFF_WK 16777216
#define OFF_WV 20971520
#define OFF_WO 25165824

__device__ __nv_bfloat16 g_h_hi[(size_t)L * HID];
__device__ __nv_bfloat16 g_h_lo[(size_t)L * HID];
__device__ __nv_bfloat16 g_w_hi[(size_t)NW_TOTAL];
__device__ __nv_bfloat16 g_w_lo[(size_t)NW_TOTAL];
__device__ __nv_bfloat16 g_a_hi[(size_t)L * HID];
__device__ __nv_bfloat16 g_a_lo[(size_t)L * HID];
__device__ __nv_bfloat16 g_qh[(size_t)L * HID];
__device__ __nv_bfloat16 g_ql[(size_t)L * HID];
__device__ __nv_bfloat16 g_kh[(size_t)L * NKV * HD];
__device__ __nv_bfloat16 g_kl[(size_t)L * NKV * HD];
__device__ __nv_bfloat16 g_vb[(size_t)L * NKV * HD];
__device__ float g_q[(size_t)L * HID];
__device__ float g_k[(size_t)L * NKV * HD];
__device__ float g_v[(size_t)L * NKV * HD];

__device__ __forceinline__ void split_bf16(float x, __nv_bfloat16& hi, __nv_bfloat16& lo) {
    hi = __float2bfloat16_rn(x);
    lo = __float2bfloat16_rn(x - __bfloat162float(hi));
}
__device__ __forceinline__ uint32_t pack_bf16(float lo, float hi) {
    __nv_bfloat162 t = __floats2bfloat162_rn(lo, hi);  // .x = lo bits [15:0]
    return *(uint32_t*)&t;
}

// ---------------------------------------------------------------------------
// cache copy — rows [L, MAXP) only (rope_kv fully writes rows [0, L))
// ---------------------------------------------------------------------------
__global__ void copy_caches_kernel(const float4* __restrict__ kin,
                                   const float4* __restrict__ vin,
                                   float4* __restrict__ kout,
                                   float4* __restrict__ vout) {
    int idx = blockIdx.x * 256 + threadIdx.x;
    const int n4 = (MAXP - L) * NKV * HD / 4;  // 524288
    const int off = L * NKV * HD / 4;
    if (idx < n4) kout[off + idx] = kin[off + idx];
    else vout[off + idx - n4] = vin[off + idx - n4];
}

// ---------------------------------------------------------------------------
// fused weight split-convert (all 4 weights, one launch)
// ---------------------------------------------------------------------------
__global__ void convert_all_kernel(const float4* __restrict__ wq,
                                   const float4* __restrict__ wk,
                                   const float4* __restrict__ wv,
                                   const float4* __restrict__ wo,
                                   __nv_bfloat16* __restrict__ hi,
                                   __nv_bfloat16* __restrict__ lo) {
    int i = blockIdx.x * 256 + threadIdx.x;  // [0, NW_TOTAL/4)
    const float4* src;
    int base;
    if (i < OFF_WK / 4) { src = wq; base = 0; }
    else if (i < OFF_WV / 4) { src = wk; base = OFF_WK / 4; }
    else if (i < OFF_WO / 4) { src = wv; base = OFF_WV / 4; }
    else { src = wo; base = OFF_WO / 4; }
    float4 v = src[i - base];
    __nv_bfloat16 h0, h1, h2, h3, l0, l1, l2, l3;
    split_bf16(v.x, h0, l0); split_bf16(v.y, h1, l1);
    split_bf16(v.z, h2, l2); split_bf16(v.w, h3, l3);
    __nv_bfloat162* hp = (__nv_bfloat162*)(hi + (size_t)i * 4);
    __nv_bfloat162* lp = (__nv_bfloat162*)(lo + (size_t)i * 4);
    hp[0] = __nv_bfloat162(h0, h1); hp[1] = __nv_bfloat162(h2, h3);
    lp[0] = __nv_bfloat162(l0, l1); lp[1] = __nv_bfloat162(l2, l3);
}

// ---------------------------------------------------------------------------
// RMSNorm -> split bf16
// ---------------------------------------------------------------------------
__global__ void __launch_bounds__(256) rmsnorm_kernel(const float* __restrict__ x,
                                                      const float* __restrict__ w) {
    int row = blockIdx.x;
    const float* xr = x + (size_t)row * HID;
    int t = threadIdx.x;
    float vals[16];
    float local = 0.f;
#pragma unroll
    for (int i = 0; i < 16; ++i) {
        float v = xr[t + i * 256];
        vals[i] = v;
        local += v * v;
    }
    __shared__ float red[8];
#pragma unroll
    for (int o = 16; o; o >>= 1) local += __shfl_xor_sync(0xffffffffu, local, o);
    if ((t & 31) == 0) red[t >> 5] = local;
    __syncthreads();
    if (t < 8) {
        float v = red[t];
#pragma unroll
        for (int o = 4; o; o >>= 1) v += __shfl_xor_sync(0xffu, v, o);
        if (t == 0) red[0] = v;
    }
    __syncthreads();
    float rms = rsqrtf(red[0] / (float)HID + 1e-5f);
    size_t base = (size_t)row * HID;
#pragma unroll
    for (int i = 0; i < 16; ++i) {
        float y = vals[i] * rms * w[t + i * 256];
        __nv_bfloat16 h, l;
        split_bf16(y, h, l);
        g_h_hi[base + t + i * 256] = h;
        g_h_lo[base + t + i * 256] = l;
    }
}

// ---------------------------------------------------------------------------
// split-bf16 GEMM via mma.sync: C[M,N] = A[M,K] B[N,K]^T (+res), K=4096
// CTA 128x256, 512 THREADS (16 warps, 4/SMSP), warp tile 32x64, K-chunk 64.
// Round 9 showed 2 warps/SMSP can't hide HMMA/LDSM latency (tensor stuck 51%,
// regs at 255). Doubling warps + halving acc regs (64/thread) targets that.
// MODE 1: fused QKV (N=6144; route q/k/v).  MODE 2: +res.
// ---------------------------------------------------------------------------
#define GSTRIDE 144
#define ATILE 18432            // 128 * 144
#define BTILE 36864            // 256 * 144
#define BOFF  36864            // 2 * ATILE
#define GSTAGE 110592          // 2*ATILE + 2*BTILE
#define GEMM_SMEM (2 * GSTAGE) // 221184
#define GTHREADS 512

template <int MODE>
__global__ void __launch_bounds__(GTHREADS, 1) mma_gemm_kernel(
    const __nv_bfloat16* __restrict__ Ah, const __nv_bfloat16* __restrict__ Al,
    const __nv_bfloat16* __restrict__ Bh, const __nv_bfloat16* __restrict__ Bl,
    float* __restrict__ C, float* __restrict__ Ck, float* __restrict__ Cvv,
    int N, const float* __restrict__ res) {
    extern __shared__ char sm[];
    const uint32_t sb = smem_u32(sm);
    const int tid = threadIdx.x;
    const int lane = tid & 31, w = tid >> 5;
    const int wm = w >> 2, wn = w & 3;          // 4 x 4 warps, warp tile 32x64
    const int bm = blockIdx.y * 128, bn = blockIdx.x * 256;

    float acc[2][8][4];
#pragma unroll
    for (int a = 0; a < 2; ++a)
#pragma unroll
        for (int b = 0; b < 8; ++b)
#pragma unroll
            for (int c = 0; c < 4; ++c) acc[a][b][c] = 0.f;

    auto issue = [&](int c, int s) {
#pragma unroll
        for (int j = 0; j < 4; ++j) {            // A: 2 terms x 1024 elems
            const int term = j >> 1;
            const int local = tid + (j & 1) * GTHREADS;  // 0..1023
            const int row = local >> 3;          // 0..127
            const int seg = local & 7;
            const __nv_bfloat16* src = term ? Al : Ah;
            const void* g = src + (size_t)(bm + row) * HID + c * 64 + seg * 8;
            uint32_t dst = sb + s * GSTAGE + term * ATILE + row * GSTRIDE + seg * 16;
            CP_ASYNC16(dst, g);
        }
#pragma unroll
        for (int j = 0; j < 8; ++j) {            // B: 2 terms x 2048 elems
            const int term = j >> 2;
            const int local = tid + (j & 3) * GTHREADS;  // 0..2047
            const int row = local >> 3;          // 0..255
            const int seg = local & 7;
            const __nv_bfloat16* src = term ? Bl : Bh;
            const void* g = src + (size_t)(bn + row) * HID + c * 64 + seg * 8;
            uint32_t dst = sb + s * GSTAGE + BOFF + term * BTILE + row * GSTRIDE + seg * 16;
            CP_ASYNC16(dst, g);
        }
    };

    auto compute = [&](int s) {
        const uint32_t base = sb + s * GSTAGE;
        const int rsel = lane & 15;
        const int csel = (lane >> 4) << 4;
#pragma unroll
        for (int ks = 0; ks < 4; ++ks) {
            uint32_t ah[2][4], al[2][4];
#pragma unroll
            for (int mt = 0; mt < 2; ++mt) {
                uint32_t ad = base + (wm * 32 + mt * 16 + rsel) * GSTRIDE + ks * 32 + csel;
                LDSM_X4(ah[mt][0], ah[mt][1], ah[mt][2], ah[mt][3], ad);
                LDSM_X4(al[mt][0], al[mt][1], al[mt][2], al[mt][3], ad + ATILE);
            }
#pragma unroll
            for (int half = 0; half < 2; ++half) {
                uint32_t bh[4][2], bl[4][2];
#pragma unroll
                for (int g = 0; g < 2; ++g) {
                    uint32_t bd = base + BOFF +
                                  (wn * 64 + (half * 2 + g) * 16 + rsel) * GSTRIDE +
                                  ks * 32 + csel;
                    uint32_t t0, t1, t2, t3;
                    LDSM_X4(t0, t1, t2, t3, bd);
                    bh[2 * g][0] = t0; bh[2 * g][1] = t2;
                    bh[2 * g + 1][0] = t1; bh[2 * g + 1][1] = t3;
                    LDSM_X4(t0, t1, t2, t3, bd + BTILE);
                    bl[2 * g][0] = t0; bl[2 * g][1] = t2;
                    bl[2 * g + 1][0] = t1; bl[2 * g + 1][1] = t3;
                }
#pragma unroll
                for (int nt = 0; nt < 4; ++nt)
#pragma unroll
                    for (int mt = 0; mt < 2; ++mt)
                        MMA_BF16(acc[mt][half * 4 + nt], ah[mt], bh[nt]);
#pragma unroll
                for (int nt = 0; nt < 4; ++nt)
#pragma unroll
                    for (int mt = 0; mt < 2; ++mt)
                        MMA_BF16(acc[mt][half * 4 + nt], ah[mt], bl[nt]);
#pragma unroll
                for (int nt = 0; nt < 4; ++nt)
#pragma unroll
                    for (int mt = 0; mt < 2; ++mt)
                        MMA_BF16(acc[mt][half * 4 + nt], al[mt], bh[nt]);
            }
        }
    };

    issue(0, 0); CP_COMMIT();
    issue(1, 1); CP_COMMIT();
#pragma unroll 1
    for (int c = 0; c < 64; ++c) {
        if (c + 1 < 64) { CP_WAIT(1); } else { CP_WAIT(0); }
        __syncthreads();
        compute(c & 1);
        if (c + 2 < 64) {
            __syncthreads();
            issue(c + 2, c & 1);
            CP_COMMIT();
        }
    }

    // epilogue: route output
    float* Cout = C;
    int ncols = N, bnl = bn;
    if (MODE == 1) {
        if (bn < 4096) { Cout = C; ncols = 4096; bnl = bn; }
        else if (bn < 5120) { Cout = Ck; ncols = 1024; bnl = bn - 4096; }
        else { Cout = Cvv; ncols = 1024; bnl = bn - 5120; }
    }
#pragma unroll
    for (int mt = 0; mt < 2; ++mt)
#pragma unroll
        for (int nt = 0; nt < 8; ++nt) {
            int row = bm + wm * 32 + mt * 16 + (lane >> 2);
            int col = bnl + wn * 64 + nt * 8 + ((lane & 3) << 1);
            size_t o0 = (size_t)row * ncols + col;
            size_t o1 = (size_t)(row + 8) * ncols + col;
            float2 v0 = make_float2(acc[mt][nt][0], acc[mt][nt][1]);
            float2 v1 = make_float2(acc[mt][nt][2], acc[mt][nt][3]);
            if (MODE == 2) {
                float2 r0 = *(const float2*)&res[o0];
                float2 r1 = *(const float2*)&res[o1];
                v0.x += r0.x; v0.y += r0.y;
                v1.x += r1.x; v1.y += r1.y;
            }
            *(float2*)&Cout[o0] = v0;
            *(float2*)&Cout[o1] = v1;
        }
}

// ---------------------------------------------------------------------------
// RoPE Q: fp32 in g_q -> scaled (1/sqrt(hd) * log2e) split bf16
// ---------------------------------------------------------------------------
__global__ void rope_q_kernel(const float* __restrict__ cosb, const float* __restrict__ sinb) {
    const float QS = 0.08838834764831845f * 1.4426950408889634f;
    int idx = blockIdx.x * 256 + threadIdx.x;
    int d = idx & 63;
    int h = (idx >> 6) & (NH - 1);
    int i = idx >> 11;
    const float* qp = g_q + (size_t)i * HID + h * HD;
    float c0 = cosb[i * HD + d], s0 = sinb[i * HD + d];
    float c1 = cosb[i * HD + d + 64], s1 = sinb[i * HD + d + 64];
    float q0 = qp[d], q1 = qp[d + 64];
    float r0 = (q0 * c0 - q1 * s0) * QS;
    float r1 = (q1 * c1 + q0 * s1) * QS;
    size_t base = (size_t)i * HID + h * HD;
    __nv_bfloat16 hh, ll;
    split_bf16(r0, hh, ll);
    g_qh[base + d] = hh; g_ql[base + d] = ll;
    split_bf16(r1, hh, ll);
    g_qh[base + d + 64] = hh; g_ql[base + d + 64] = ll;
}

// RoPE K + scatter fp32 caches + split bf16 K, bf16 V (position = row index)
__global__ void rope_kv_kernel(const float* __restrict__ cosb, const float* __restrict__ sinb,
                               float* __restrict__ kc_out, float* __restrict__ vc_out) {
    int idx = blockIdx.x * 256 + threadIdx.x;
    int d = idx & 63;
    int h = (idx >> 6) & (NKV - 1);
    int i = idx >> 9;
    size_t base = (size_t)i * (NKV * HD) + h * HD;
    float c0 = cosb[i * HD + d], s0 = sinb[i * HD + d];
    float c1 = cosb[i * HD + d + 64], s1 = sinb[i * HD + d + 64];
    float k0 = g_k[base + d], k1 = g_k[base + d + 64];
    float k0n = k0 * c0 - k1 * s0;
    float k1n = k1 * c1 + k0 * s1;
    kc_out[base + d] = k0n;
    kc_out[base + d + 64] = k1n;
    __nv_bfloat16 hh, ll;
    split_bf16(k0n, hh, ll);
    g_kh[base + d] = hh; g_kl[base + d] = ll;
    split_bf16(k1n, hh, ll);
    g_kh[base + d + 64] = hh; g_kl[base + d + 64] = ll;
    float v0 = g_v[base + d], v1 = g_v[base + d + 64];
    vc_out[base + d] = v0;
    vc_out[base + d + 64] = v1;
    g_vb[base + d] = __float2bfloat16_rn(v0);
    g_vb[base + d + 64] = __float2bfloat16_rn(v1);
}

// ---------------------------------------------------------------------------
// Flash attention via mma.sync: BM=128 (8 warps x m16), BN=64, HD=128.
// QK^T split bf16, term-major in N-halves of 4; softmax fp32 exp2; PV bf16.
// Split cp.async waits: V load overlaps the whole S-phase.
// ---------------------------------------------------------------------------
#define FSTRIDE 272
#define FQH 0
#define FQL 34816
#define FKH 69632
#define FKL 87040
#define FV 104448
#define FLASH_SMEM 121856

__global__ void __launch_bounds__(256, 1) flash_kernel() {
    extern __shared__ char sm[];
    const uint32_t sb = smem_u32(sm);
    const int tid = threadIdx.x;
    const int lane = tid & 31, w = tid >> 5;
    const int qt = gridDim.x - 1 - blockIdx.x;  // heavy tiles first
    const int head = blockIdx.y;
    const int kvh = head >> 2;
    const int rsel = lane & 15;
    const int csel = (lane >> 4) << 4;

#pragma unroll
    for (int j = 0; j < 16; ++j) {
        const int term = j >> 3;
        const int local = tid + (j & 7) * 256;
        const int row = local >> 4;
        const int seg = local & 15;
        const __nv_bfloat16* src = (term ? g_ql : g_qh);
        const void* g = src + (size_t)(qt * 128 + row) * HID + head * HD + seg * 8;
        uint32_t dst = sb + (term ? FQL : FQH) + row * FSTRIDE + seg * 16;
        CP_ASYNC16(dst, g);
    }
    CP_COMMIT();

    float o_[16][4];
#pragma unroll
    for (int n = 0; n < 16; ++n)
#pragma unroll
        for (int c = 0; c < 4; ++c) o_[n][c] = 0.f;
    float m_[2] = {-1e30f, -1e30f};
    float l_[2] = {0.f, 0.f};

    const int kt_end = 2 * qt + 2;
#pragma unroll 1
    for (int kt = 0; kt < kt_end; ++kt) {
        __syncthreads();
#pragma unroll
        for (int j = 0; j < 8; ++j) {
            const int t = j >> 2;
            const int local = tid + (j & 3) * 256;
            const int row = local >> 4;
            const int seg = local & 15;
            const __nv_bfloat16* src = (t == 0) ? g_kh : g_kl;
            const void* g = src + (size_t)(kt * 64 + row) * (NKV * HD) + kvh * HD + seg * 8;
            uint32_t dst = sb + ((t == 0) ? FKH : FKL) + row * FSTRIDE + seg * 16;
            CP_ASYNC16(dst, g);
        }
        CP_COMMIT();
#pragma unroll
        for (int j = 0; j < 4; ++j) {
            const int local = tid + j * 256;
            const int row = local >> 4;
            const int seg = local & 15;
            const void* g = g_vb + (size_t)(kt * 64 + row) * (NKV * HD) + kvh * HD + seg * 8;
            uint32_t dst = sb + FV + row * FSTRIDE + seg * 16;
            CP_ASYNC16(dst, g);
        }
        CP_COMMIT();

        CP_WAIT(1);
        __syncthreads();

        float s[8][4];
#pragma unroll
        for (int n = 0; n < 8; ++n)
#pragma unroll
            for (int c = 0; c < 4; ++c) s[n][c] = 0.f;
#pragma unroll
        for (int ks = 0; ks < 8; ++ks) {
            uint32_t ah[4], al[4];
            uint32_t aaddr = sb + FQH + (w * 16 + rsel) * FSTRIDE + ks * 32 + csel;
            LDSM_X4(ah[0], ah[1], ah[2], ah[3], aaddr);
            LDSM_X4(al[0], al[1], al[2], al[3], aaddr + (FQL - FQH));
#pragma unroll
            for (int half = 0; half < 2; ++half) {
                uint32_t bh[4][2], bl[4][2];
#pragma unroll
                for (int g = 0; g < 2; ++g) {
                    uint32_t bd = sb + FKH +
                                  ((half * 2 + g) * 16 + rsel) * FSTRIDE + ks * 32 + csel;
                    uint32_t t0, t1, t2, t3;
                    LDSM_X4(t0, t1, t2, t3, bd);
                    bh[2 * g][0] = t0; bh[2 * g][1] = t2;
                    bh[2 * g + 1][0] = t1; bh[2 * g + 1][1] = t3;
                    LDSM_X4(t0, t1, t2, t3, bd + (FKL - FKH));
                    bl[2 * g][0] = t0; bl[2 * g][1] = t2;
                    bl[2 * g + 1][0] = t1; bl[2 * g + 1][1] = t3;
                }
#pragma unroll
                for (int n = 0; n < 4; ++n) MMA_BF16(s[half * 4 + n], ah, bh[n]);
#pragma unroll
                for (int n = 0; n < 4; ++n) MMA_BF16(s[half * 4 + n], ah, bl[n]);
#pragma unroll
                for (int n = 0; n < 4; ++n) MMA_BF16(s[half * 4 + n], al, bh[n]);
            }
        }

        if (kt >= 2 * qt) {
            const int r0g = qt * 128 + w * 16 + (lane >> 2);
#pragma unroll
            for (int j = 0; j < 8; ++j) {
                int cb = kt * 64 + j * 8 + ((lane & 3) << 1);
                if (cb > r0g) s[j][0] = -1e30f;
                if (cb + 1 > r0g) s[j][1] = -1e30f;
                if (cb > r0g + 8) s[j][2] = -1e30f;
                if (cb + 1 > r0g + 8) s[j][3] = -1e30f;
            }
        }

#pragma unroll
        for (int i = 0; i < 2; ++i) {
            float mt_ = -1e30f;
#pragma unroll
            for (int j = 0; j < 8; ++j)
                mt_ = fmaxf(mt_, fmaxf(s[j][2 * i], s[j][2 * i + 1]));
            mt_ = fmaxf(mt_, __shfl_xor_sync(0xffffffffu, mt_, 1));
            mt_ = fmaxf(mt_, __shfl_xor_sync(0xffffffffu, mt_, 2));
            float mn = fmaxf(m_[i], mt_);
            float corr = fast_exp2(m_[i] - mn);
            m_[i] = mn;
            float rs = 0.f;
#pragma unroll
            for (int j = 0; j < 8; ++j) {
                float p0 = fast_exp2(s[j][2 * i] - mn);
                float p1 = fast_exp2(s[j][2 * i + 1] - mn);
                s[j][2 * i] = p0;
                s[j][2 * i + 1] = p1;
                rs += p0 + p1;
            }
            rs += __shfl_xor_sync(0xffffffffu, rs, 1);
            rs += __shfl_xor_sync(0xffffffffu, rs, 2);
            l_[i] = l_[i] * corr + rs;
#pragma unroll
            for (int n = 0; n < 16; ++n) {
                o_[n][2 * i] *= corr;
                o_[n][2 * i + 1] *= corr;
            }
        }

        uint32_t pa[4][4];
#pragma unroll
        for (int t = 0; t < 4; ++t) {
            pa[t][0] = pack_bf16(s[2 * t][0], s[2 * t][1]);
            pa[t][1] = pack_bf16(s[2 * t][2], s[2 * t][3]);
            pa[t][2] = pack_bf16(s[2 * t + 1][0], s[2 * t + 1][1]);
            pa[t][3] = pack_bf16(s[2 * t + 1][2], s[2 * t + 1][3]);
        }

        CP_WAIT(0);
        __syncthreads();

#pragma unroll
        for (int t = 0; t < 4; ++t) {
#pragma unroll
            for (int g = 0; g < 8; ++g) {
                uint32_t vaddr = sb + FV + (t * 16 + rsel) * FSTRIDE +
                                 (g * 16 + ((lane >> 4) << 3)) * 2;
                uint32_t t0, t1, t2, t3;
                LDSM_X4_T(t0, t1, t2, t3, vaddr);
                uint32_t b0[2] = {t0, t1}, b1[2] = {t2, t3};
                MMA_BF16(o_[2 * g], pa[t], b0);
                MMA_BF16(o_[2 * g + 1], pa[t], b1);
            }
        }
    }

    const float inv0 = 1.f / l_[0];
    const float inv1 = 1.f / l_[1];
    const int r0g = qt * 128 + w * 16 + (lane >> 2);
#pragma unroll
    for (int nt = 0; nt < 16; ++nt) {
        int col = head * HD + nt * 8 + ((lane & 3) << 1);
        size_t o0 = (size_t)r0g * HID + col;
        size_t o1 = o0 + (size_t)8 * HID;
        __nv_bfloat16 h0, l0, h1, l1;
        split_bf16(o_[nt][0] * inv0, h0, l0);
        split_bf16(o_[nt][1] * inv0, h1, l1);
        *(__nv_bfloat162*)(g_a_hi + o0) = __nv_bfloat162(h0, h1);
        *(__nv_bfloat162*)(g_a_lo + o0) = __nv_bfloat162(l0, l1);
        split_bf16(o_[nt][2] * inv1, h0, l0);
        split_bf16(o_[nt][3] * inv1, h1, l1);
        *(__nv_bfloat162*)(g_a_hi + o1) = __nv_bfloat162(h0, h1);
        *(__nv_bfloat162*)(g_a_lo + o1) = __nv_bfloat162(l0, l1);
    }
}

// ---------------------------------------------------------------------------
// launch
// ---------------------------------------------------------------------------
extern "C" void kernel_launch(void* const* d_in, const int* in_sizes, int n_in,
                              void* d_out, int out_size) {
    const float* x = (const float*)d_in[0];
    const float* cosb = (const float*)d_in[1];
    const float* sinb = (const float*)d_in[2];
    // d_in[3] position_ids (arange; not dereferenced), d_in[4] seq_len
    const float* kc_in = (const float*)d_in[5];
    const float* vc_in = (const float*)d_in[6];
    const float* lnw = (const float*)d_in[7];
    const float* Wq = (const float*)d_in[8];
    const float* Wk = (const float*)d_in[9];
    const float* Wv = (const float*)d_in[10];
    const float* Wo = (const float*)d_in[11];

    float* out = (float*)d_out;
    float* kc_out = out + (size_t)L * HID;
    float* vc_out = kc_out + (size_t)MAXP * NKV * HD;

    __nv_bfloat16 *pHh, *pHl, *pWh, *pWl, *pAh, *pAl;
    float *pQ, *pK, *pV;
    cudaGetSymbolAddress((void**)&pHh, g_h_hi);
    cudaGetSymbolAddress((void**)&pHl, g_h_lo);
    cudaGetSymbolAddress((void**)&pWh, g_w_hi);
    cudaGetSymbolAddress((void**)&pWl, g_w_lo);
    cudaGetSymbolAddress((void**)&pAh, g_a_hi);
    cudaGetSymbolAddress((void**)&pAl, g_a_lo);
    cudaGetSymbolAddress((void**)&pQ, g_q);
    cudaGetSymbolAddress((void**)&pK, g_k);
    cudaGetSymbolAddress((void**)&pV, g_v);

    // caches: rows [L, MAXP) copied; rows [0, L) fully written by rope_kv
    copy_caches_kernel<<<(2 * (MAXP - L) * NKV * HD / 4) / 256, 256>>>(
        (const float4*)kc_in, (const float4*)vc_in, (float4*)kc_out, (float4*)vc_out);

    convert_all_kernel<<<(NW_TOTAL / 4) / 256, 256>>>(
        (const float4*)Wq, (const float4*)Wk, (const float4*)Wv, (const float4*)Wo, pWh, pWl);

    rmsnorm_kernel<<<L, 256>>>(x, lnw);

    cudaFuncSetAttribute((const void*)mma_gemm_kernel<1>,
                         cudaFuncAttributeMaxDynamicSharedMemorySize, GEMM_SMEM);
    cudaFuncSetAttribute((const void*)mma_gemm_kernel<2>,
                         cudaFuncAttributeMaxDynamicSharedMemorySize, GEMM_SMEM);

    // fused Q+K+V projection: N = 4096 + 1024 + 1024 = 6144, grid (24, 16)
    mma_gemm_kernel<1><<<dim3(6144 / 256, L / 128), GTHREADS, GEMM_SMEM>>>(
        pHh, pHl, pWh, pWl, pQ, pK, pV, 6144, nullptr);

    rope_q_kernel<<<(L * NH * 64) / 256, 256>>>(cosb, sinb);
    rope_kv_kernel<<<(L * NKV * 64) / 256, 256>>>(cosb, sinb, kc_out, vc_out);

    cudaFuncSetAttribute(flash_kernel, cudaFuncAttributeMaxDynamicSharedMemorySize, FLASH_SMEM);
    flash_kernel<<<dim3(L / 128, NH), 256, FLASH_SMEM>>>();

    mma_gemm_kernel<2><<<dim3(HID / 256, L / 128), GTHREADS, GEMM_SMEM>>>(
        pAh, pAl, pWh + OFF_WO, pWl + OFF_WO, out, nullptr, nullptr, HID, x);
}